// round 6
// baseline (speedup 1.0000x reference)
#include <cuda_runtime.h>
#include <cstdint>

// ---------------------------------------------------------------------------
// RegionProposalNetwork fused kernel (round 2 baseline, f32x2 dual-FMA path)
//
//   feat = ReLU( conv3x3(x, W1) + b1 )        [B,512,H,W]
//   cls  = Wc @ feat + bc  -> [b,y,x,18]       (out region 0)
//   box  = Wb @ feat + bb  -> [b,y,x,36]       (out region 1, offset B*H*W*18)
//
// B=4 C=256 H=200 W=336 OC=512
// ---------------------------------------------------------------------------

#define B_      4
#define C_IN    256
#define H_      200
#define W_      336
#define OC      512
#define NTAP    9
#define HW      (H_ * W_)

#define TILE_X    56                  // 336 = 6 * 56 exactly
#define NTHREADS  448                 // 64 oc-groups x 7 px-groups
#define CC        64                  // input-channel chunk held in smem
#define NCHUNK    (C_IN / CC)         // 4
#define IN_COLS   (TILE_X + 2)        // 58 (1-px halo each side)
#define IN_SZ     (CC * 3 * IN_COLS)  // floats per chunk = 11136

#define FEAT_STRIDE 516               // 512 + 4 pad: conflict-free float4 reads
#define SMEM_FLOATS (IN_SZ + TILE_X * FEAT_STRIDE)
#define SMEM_BYTES  (SMEM_FLOATS * 4) // 160,128 B

#define CLS_CH   18
#define HEAD_CH  54
#define CLS_TOTAL ((size_t)B_ * HW * CLS_CH)

// Transposed conv weights: g_wt[tap][c][o], o contiguous (coalesced + pair-ready)
__device__ float g_wt[NTAP * C_IN * OC];

__global__ void prep_weights(const float* __restrict__ W1) {
    int idx = blockIdx.x * blockDim.x + threadIdx.x;
    const int total = NTAP * C_IN * OC;
    if (idx >= total) return;
    int o   = idx % OC;
    int c   = (idx / OC) % C_IN;
    int tap = idx / (OC * C_IN);
    // W1 layout [OC, C, 3, 3]
    g_wt[idx] = W1[(o * C_IN + c) * 9 + tap];
}

// packed dual-fp32 FMA (Blackwell f32x2 pipe; 2x FFMA throughput)
__device__ __forceinline__ void fma2(unsigned long long& d,
                                     unsigned long long a,
                                     unsigned long long b) {
    asm("fma.rn.f32x2 %0, %1, %2, %0;" : "+l"(d) : "l"(a), "l"(b));
}
__device__ __forceinline__ unsigned long long dup_f32(float v) {
    unsigned long long r;
    asm("mov.b64 %0, {%1, %1};" : "=l"(r) : "f"(v));
    return r;
}

__global__ void __launch_bounds__(NTHREADS, 1)
rpn_fused(const float* __restrict__ x,
          const float* __restrict__ b1,
          const float* __restrict__ Wc,
          const float* __restrict__ bc,
          const float* __restrict__ Wb,
          const float* __restrict__ bb,
          float* __restrict__ out) {
    extern __shared__ float smem[];
    float* in_s = smem;              // [CC][3][IN_COLS]
    float* feat = smem + IN_SZ;      // [TILE_X][FEAT_STRIDE]

    const int tid = threadIdx.x;
    const int ocg = tid & 63;        // 0..63  (oc pair group)
    const int pxg = tid >> 6;        // 0..6   (8-pixel group)
    const int x0  = blockIdx.x * TILE_X;
    const int y   = blockIdx.y;
    const int b   = blockIdx.z;

    // 4 oc-pairs x 8 pixels of f32x2 accumulators (pair = channels o0, o0+1)
    unsigned long long acc[4][8];
#pragma unroll
    for (int i = 0; i < 4; i++)
#pragma unroll
        for (int j = 0; j < 8; j++) acc[i][j] = 0ull;

    const float* xin = x + (size_t)b * C_IN * HW;

    for (int ch = 0; ch < NCHUNK; ch++) {
        __syncthreads();
        // stage one 64-channel chunk of the 3-row input slab (zero-padded halo)
        for (int i = tid; i < IN_SZ; i += NTHREADS) {
            int col = i % IN_COLS;
            int r   = (i / IN_COLS) % 3;
            int c   = i / (IN_COLS * 3);
            int gx  = x0 - 1 + col;
            int gy  = y - 1 + r;
            float v = 0.0f;
            if ((unsigned)gx < (unsigned)W_ && (unsigned)gy < (unsigned)H_)
                v = xin[(size_t)(ch * CC + c) * HW + (size_t)gy * W_ + gx];
            in_s[i] = v;
        }
        __syncthreads();

        for (int cl = 0; cl < CC; cl++) {
            const float* srow  = in_s + cl * 3 * IN_COLS + pxg * 8;
            const float* wrowc = g_wt + (size_t)(ch * CC + cl) * OC;
#pragma unroll
            for (int ky = 0; ky < 3; ky++) {
                float xv[10];
#pragma unroll
                for (int t = 0; t < 10; t++) xv[t] = srow[ky * IN_COLS + t];
#pragma unroll
                for (int kx = 0; kx < 3; kx++) {
                    const int tap = ky * 3 + kx;
                    const float* wp = wrowc + (size_t)tap * C_IN * OC + ocg * 2;
                    unsigned long long wv[4];
#pragma unroll
                    for (int i = 0; i < 4; i++)
                        wv[i] = *reinterpret_cast<const unsigned long long*>(wp + 128 * i);
#pragma unroll
                    for (int j = 0; j < 8; j++) {
                        unsigned long long xx = dup_f32(xv[j + kx]);
#pragma unroll
                        for (int i = 0; i < 4; i++) fma2(acc[i][j], wv[i], xx);
                    }
                }
            }
        }
    }

    // bias + ReLU, scatter feat tile to smem (px-major for float4 head reads)
#pragma unroll
    for (int i = 0; i < 4; i++) {
        const int o0 = ocg * 2 + 128 * i;
        const float bia0 = b1[o0];
        const float bia1 = b1[o0 + 1];
#pragma unroll
        for (int j = 0; j < 8; j++) {
            const int px = pxg * 8 + j;
            float lo = __uint_as_float((unsigned)(acc[i][j] & 0xffffffffull));
            float hi = __uint_as_float((unsigned)(acc[i][j] >> 32));
            feat[px * FEAT_STRIDE + o0]     = fmaxf(lo + bia0, 0.0f);
            feat[px * FEAT_STRIDE + o0 + 1] = fmaxf(hi + bia1, 0.0f);
        }
    }
    __syncthreads();

    // fused 1x1 heads: 54 outputs per pixel (18 cls + 36 box)
    const int px = tid % TILE_X;     // 0..55
    const int hb = tid / TILE_X;     // 0..7
    const int nho = (hb < 6) ? 7 : 6;  // ho = hb + 8k < 54

    const float* fp = feat + px * FEAT_STRIDE;
    float hacc[7];
    const float* wrow[7];
#pragma unroll
    for (int k = 0; k < 7; k++) {
        if (k < nho) {
            const int ho = hb + 8 * k;
            if (ho < CLS_CH) { wrow[k] = Wc + ho * OC;            hacc[k] = bc[ho]; }
            else             { wrow[k] = Wb + (ho - CLS_CH) * OC; hacc[k] = bb[ho - CLS_CH]; }
        } else { wrow[k] = Wc; hacc[k] = 0.0f; }
    }

    for (int o = 0; o < OC; o += 4) {
        const float4 f = *reinterpret_cast<const float4*>(fp + o);
#pragma unroll
        for (int k = 0; k < 7; k++) {
            if (k < nho) {
                const float4 w = *reinterpret_cast<const float4*>(wrow[k] + o);
                hacc[k] += f.x * w.x + f.y * w.y + f.z * w.z + f.w * w.w;
            }
        }
    }

    const size_t pix = ((size_t)(b * H_ + y)) * W_ + (x0 + px);
#pragma unroll
    for (int k = 0; k < 7; k++) {
        if (k < nho) {
            const int ho = hb + 8 * k;
            if (ho < CLS_CH) out[pix * CLS_CH + ho] = hacc[k];
            else             out[CLS_TOTAL + pix * 36 + (ho - CLS_CH)] = hacc[k];
        }
    }
}

extern "C" void kernel_launch(void* const* d_in, const int* in_sizes, int n_in,
                              void* d_out, int out_size) {
    const float* xf  = (const float*)d_in[0];
    const float* W1  = (const float*)d_in[1];
    const float* b1v = (const float*)d_in[2];
    const float* Wc  = (const float*)d_in[3];
    const float* bc  = (const float*)d_in[4];
    const float* Wb  = (const float*)d_in[5];
    const float* bb  = (const float*)d_in[6];
    float* out = (float*)d_out;

    (void)in_sizes; (void)n_in; (void)out_size;

    // transpose conv weights into [tap][c][o] (coalesced, pair-contiguous)
    const int wtotal = NTAP * C_IN * OC;
    prep_weights<<<(wtotal + 255) / 256, 256>>>(W1);

    // executes immediately (not a stream op) — legal during graph capture
    cudaFuncSetAttribute(rpn_fused,
                         cudaFuncAttributeMaxDynamicSharedMemorySize, SMEM_BYTES);

    dim3 grid(W_ / TILE_X, H_, B_);   // 6 x 200 x 4 = 4800 blocks
    rpn_fused<<<grid, NTHREADS, SMEM_BYTES>>>(xf, b1v, Wc, bc, Wb, bb, out);
}

// round 7
// speedup vs baseline: 1.0005x; 1.0005x over previous
#include <cuda_runtime.h>
#include <cstdint>

// ---------------------------------------------------------------------------
// RegionProposalNetwork fused kernel (round 2 baseline, f32x2 dual-FMA path)
//
//   feat = ReLU( conv3x3(x, W1) + b1 )        [B,512,H,W]
//   cls  = Wc @ feat + bc  -> [b,y,x,18]       (out region 0)
//   box  = Wb @ feat + bb  -> [b,y,x,36]       (out region 1, offset B*H*W*18)
//
// B=4 C=256 H=200 W=336 OC=512
// ---------------------------------------------------------------------------

#define B_      4
#define C_IN    256
#define H_      200
#define W_      336
#define OC      512
#define NTAP    9
#define HW      (H_ * W_)

#define TILE_X    56                  // 336 = 6 * 56 exactly
#define NTHREADS  448                 // 64 oc-groups x 7 px-groups
#define CC        64                  // input-channel chunk held in smem
#define NCHUNK    (C_IN / CC)         // 4
#define IN_COLS   (TILE_X + 2)        // 58 (1-px halo each side)
#define IN_SZ     (CC * 3 * IN_COLS)  // floats per chunk = 11136

#define FEAT_STRIDE 516               // 512 + 4 pad: conflict-free float4 reads
#define SMEM_FLOATS (IN_SZ + TILE_X * FEAT_STRIDE)
#define SMEM_BYTES  (SMEM_FLOATS * 4) // 160,128 B

#define CLS_CH   18
#define HEAD_CH  54
#define CLS_TOTAL ((size_t)B_ * HW * CLS_CH)

// Transposed conv weights: g_wt[tap][c][o], o contiguous (coalesced + pair-ready)
__device__ float g_wt[NTAP * C_IN * OC];

__global__ void prep_weights(const float* __restrict__ W1) {
    int idx = blockIdx.x * blockDim.x + threadIdx.x;
    const int total = NTAP * C_IN * OC;
    if (idx >= total) return;
    int o   = idx % OC;
    int c   = (idx / OC) % C_IN;
    int tap = idx / (OC * C_IN);
    // W1 layout [OC, C, 3, 3]
    g_wt[idx] = W1[(o * C_IN + c) * 9 + tap];
}

// packed dual-fp32 FMA (Blackwell f32x2 pipe; 2x FFMA throughput)
__device__ __forceinline__ void fma2(unsigned long long& d,
                                     unsigned long long a,
                                     unsigned long long b) {
    asm("fma.rn.f32x2 %0, %1, %2, %0;" : "+l"(d) : "l"(a), "l"(b));
}
__device__ __forceinline__ unsigned long long dup_f32(float v) {
    unsigned long long r;
    asm("mov.b64 %0, {%1, %1};" : "=l"(r) : "f"(v));
    return r;
}

__global__ void __launch_bounds__(NTHREADS, 1)
rpn_fused(const float* __restrict__ x,
          const float* __restrict__ b1,
          const float* __restrict__ Wc,
          const float* __restrict__ bc,
          const float* __restrict__ Wb,
          const float* __restrict__ bb,
          float* __restrict__ out) {
    extern __shared__ float smem[];
    float* in_s = smem;              // [CC][3][IN_COLS]
    float* feat = smem + IN_SZ;      // [TILE_X][FEAT_STRIDE]

    const int tid = threadIdx.x;
    const int ocg = tid & 63;        // 0..63  (oc pair group)
    const int pxg = tid >> 6;        // 0..6   (8-pixel group)
    const int x0  = blockIdx.x * TILE_X;
    const int y   = blockIdx.y;
    const int b   = blockIdx.z;

    // 4 oc-pairs x 8 pixels of f32x2 accumulators (pair = channels o0, o0+1)
    unsigned long long acc[4][8];
#pragma unroll
    for (int i = 0; i < 4; i++)
#pragma unroll
        for (int j = 0; j < 8; j++) acc[i][j] = 0ull;

    const float* xin = x + (size_t)b * C_IN * HW;

    for (int ch = 0; ch < NCHUNK; ch++) {
        __syncthreads();
        // stage one 64-channel chunk of the 3-row input slab (zero-padded halo)
        for (int i = tid; i < IN_SZ; i += NTHREADS) {
            int col = i % IN_COLS;
            int r   = (i / IN_COLS) % 3;
            int c   = i / (IN_COLS * 3);
            int gx  = x0 - 1 + col;
            int gy  = y - 1 + r;
            float v = 0.0f;
            if ((unsigned)gx < (unsigned)W_ && (unsigned)gy < (unsigned)H_)
                v = xin[(size_t)(ch * CC + c) * HW + (size_t)gy * W_ + gx];
            in_s[i] = v;
        }
        __syncthreads();

        for (int cl = 0; cl < CC; cl++) {
            const float* srow  = in_s + cl * 3 * IN_COLS + pxg * 8;
            const float* wrowc = g_wt + (size_t)(ch * CC + cl) * OC;
#pragma unroll
            for (int ky = 0; ky < 3; ky++) {
                float xv[10];
#pragma unroll
                for (int t = 0; t < 10; t++) xv[t] = srow[ky * IN_COLS + t];
#pragma unroll
                for (int kx = 0; kx < 3; kx++) {
                    const int tap = ky * 3 + kx;
                    const float* wp = wrowc + (size_t)tap * C_IN * OC + ocg * 2;
                    unsigned long long wv[4];
#pragma unroll
                    for (int i = 0; i < 4; i++)
                        wv[i] = *reinterpret_cast<const unsigned long long*>(wp + 128 * i);
#pragma unroll
                    for (int j = 0; j < 8; j++) {
                        unsigned long long xx = dup_f32(xv[j + kx]);
#pragma unroll
                        for (int i = 0; i < 4; i++) fma2(acc[i][j], wv[i], xx);
                    }
                }
            }
        }
    }

    // bias + ReLU, scatter feat tile to smem (px-major for float4 head reads)
#pragma unroll
    for (int i = 0; i < 4; i++) {
        const int o0 = ocg * 2 + 128 * i;
        const float bia0 = b1[o0];
        const float bia1 = b1[o0 + 1];
#pragma unroll
        for (int j = 0; j < 8; j++) {
            const int px = pxg * 8 + j;
            float lo = __uint_as_float((unsigned)(acc[i][j] & 0xffffffffull));
            float hi = __uint_as_float((unsigned)(acc[i][j] >> 32));
            feat[px * FEAT_STRIDE + o0]     = fmaxf(lo + bia0, 0.0f);
            feat[px * FEAT_STRIDE + o0 + 1] = fmaxf(hi + bia1, 0.0f);
        }
    }
    __syncthreads();

    // fused 1x1 heads: 54 outputs per pixel (18 cls + 36 box)
    const int px = tid % TILE_X;     // 0..55
    const int hb = tid / TILE_X;     // 0..7
    const int nho = (hb < 6) ? 7 : 6;  // ho = hb + 8k < 54

    const float* fp = feat + px * FEAT_STRIDE;
    float hacc[7];
    const float* wrow[7];
#pragma unroll
    for (int k = 0; k < 7; k++) {
        if (k < nho) {
            const int ho = hb + 8 * k;
            if (ho < CLS_CH) { wrow[k] = Wc + ho * OC;            hacc[k] = bc[ho]; }
            else             { wrow[k] = Wb + (ho - CLS_CH) * OC; hacc[k] = bb[ho - CLS_CH]; }
        } else { wrow[k] = Wc; hacc[k] = 0.0f; }
    }

    for (int o = 0; o < OC; o += 4) {
        const float4 f = *reinterpret_cast<const float4*>(fp + o);
#pragma unroll
        for (int k = 0; k < 7; k++) {
            if (k < nho) {
                const float4 w = *reinterpret_cast<const float4*>(wrow[k] + o);
                hacc[k] += f.x * w.x + f.y * w.y + f.z * w.z + f.w * w.w;
            }
        }
    }

    const size_t pix = ((size_t)(b * H_ + y)) * W_ + (x0 + px);
#pragma unroll
    for (int k = 0; k < 7; k++) {
        if (k < nho) {
            const int ho = hb + 8 * k;
            if (ho < CLS_CH) out[pix * CLS_CH + ho] = hacc[k];
            else             out[CLS_TOTAL + pix * 36 + (ho - CLS_CH)] = hacc[k];
        }
    }
}

extern "C" void kernel_launch(void* const* d_in, const int* in_sizes, int n_in,
                              void* d_out, int out_size) {
    const float* xf  = (const float*)d_in[0];
    const float* W1  = (const float*)d_in[1];
    const float* b1v = (const float*)d_in[2];
    const float* Wc  = (const float*)d_in[3];
    const float* bc  = (const float*)d_in[4];
    const float* Wb  = (const float*)d_in[5];
    const float* bb  = (const float*)d_in[6];
    float* out = (float*)d_out;

    (void)in_sizes; (void)n_in; (void)out_size;

    // transpose conv weights into [tap][c][o] (coalesced, pair-contiguous)
    const int wtotal = NTAP * C_IN * OC;
    prep_weights<<<(wtotal + 255) / 256, 256>>>(W1);

    // executes immediately (not a stream op) — legal during graph capture
    cudaFuncSetAttribute(rpn_fused,
                         cudaFuncAttributeMaxDynamicSharedMemorySize, SMEM_BYTES);

    dim3 grid(W_ / TILE_X, H_, B_);   // 6 x 200 x 4 = 4800 blocks
    rpn_fused<<<grid, NTHREADS, SMEM_BYTES>>>(xf, b1v, Wc, bc, Wb, bb, out);
}

// round 11
// speedup vs baseline: 1.0005x; 1.0000x over previous
#include <cuda_runtime.h>
#include <cstdint>

// ---------------------------------------------------------------------------
// RegionProposalNetwork fused kernel (round 2 baseline, f32x2 dual-FMA path)
//
//   feat = ReLU( conv3x3(x, W1) + b1 )        [B,512,H,W]
//   cls  = Wc @ feat + bc  -> [b,y,x,18]       (out region 0)
//   box  = Wb @ feat + bb  -> [b,y,x,36]       (out region 1, offset B*H*W*18)
//
// B=4 C=256 H=200 W=336 OC=512
// ---------------------------------------------------------------------------

#define B_      4
#define C_IN    256
#define H_      200
#define W_      336
#define OC      512
#define NTAP    9
#define HW      (H_ * W_)

#define TILE_X    56                  // 336 = 6 * 56 exactly
#define NTHREADS  448                 // 64 oc-groups x 7 px-groups
#define CC        64                  // input-channel chunk held in smem
#define NCHUNK    (C_IN / CC)         // 4
#define IN_COLS   (TILE_X + 2)        // 58 (1-px halo each side)
#define IN_SZ     (CC * 3 * IN_COLS)  // floats per chunk = 11136

#define FEAT_STRIDE 516               // 512 + 4 pad: conflict-free float4 reads
#define SMEM_FLOATS (IN_SZ + TILE_X * FEAT_STRIDE)
#define SMEM_BYTES  (SMEM_FLOATS * 4) // 160,128 B

#define CLS_CH   18
#define HEAD_CH  54
#define CLS_TOTAL ((size_t)B_ * HW * CLS_CH)

// Transposed conv weights: g_wt[tap][c][o], o contiguous (coalesced + pair-ready)
__device__ float g_wt[NTAP * C_IN * OC];

__global__ void prep_weights(const float* __restrict__ W1) {
    int idx = blockIdx.x * blockDim.x + threadIdx.x;
    const int total = NTAP * C_IN * OC;
    if (idx >= total) return;
    int o   = idx % OC;
    int c   = (idx / OC) % C_IN;
    int tap = idx / (OC * C_IN);
    // W1 layout [OC, C, 3, 3]
    g_wt[idx] = W1[(o * C_IN + c) * 9 + tap];
}

// packed dual-fp32 FMA (Blackwell f32x2 pipe; 2x FFMA throughput)
__device__ __forceinline__ void fma2(unsigned long long& d,
                                     unsigned long long a,
                                     unsigned long long b) {
    asm("fma.rn.f32x2 %0, %1, %2, %0;" : "+l"(d) : "l"(a), "l"(b));
}
__device__ __forceinline__ unsigned long long dup_f32(float v) {
    unsigned long long r;
    asm("mov.b64 %0, {%1, %1};" : "=l"(r) : "f"(v));
    return r;
}

__global__ void __launch_bounds__(NTHREADS, 1)
rpn_fused(const float* __restrict__ x,
          const float* __restrict__ b1,
          const float* __restrict__ Wc,
          const float* __restrict__ bc,
          const float* __restrict__ Wb,
          const float* __restrict__ bb,
          float* __restrict__ out) {
    extern __shared__ float smem[];
    float* in_s = smem;              // [CC][3][IN_COLS]
    float* feat = smem + IN_SZ;      // [TILE_X][FEAT_STRIDE]

    const int tid = threadIdx.x;
    const int ocg = tid & 63;        // 0..63  (oc pair group)
    const int pxg = tid >> 6;        // 0..6   (8-pixel group)
    const int x0  = blockIdx.x * TILE_X;
    const int y   = blockIdx.y;
    const int b   = blockIdx.z;

    // 4 oc-pairs x 8 pixels of f32x2 accumulators (pair = channels o0, o0+1)
    unsigned long long acc[4][8];
#pragma unroll
    for (int i = 0; i < 4; i++)
#pragma unroll
        for (int j = 0; j < 8; j++) acc[i][j] = 0ull;

    const float* xin = x + (size_t)b * C_IN * HW;

    for (int ch = 0; ch < NCHUNK; ch++) {
        __syncthreads();
        // stage one 64-channel chunk of the 3-row input slab (zero-padded halo)
        for (int i = tid; i < IN_SZ; i += NTHREADS) {
            int col = i % IN_COLS;
            int r   = (i / IN_COLS) % 3;
            int c   = i / (IN_COLS * 3);
            int gx  = x0 - 1 + col;
            int gy  = y - 1 + r;
            float v = 0.0f;
            if ((unsigned)gx < (unsigned)W_ && (unsigned)gy < (unsigned)H_)
                v = xin[(size_t)(ch * CC + c) * HW + (size_t)gy * W_ + gx];
            in_s[i] = v;
        }
        __syncthreads();

        for (int cl = 0; cl < CC; cl++) {
            const float* srow  = in_s + cl * 3 * IN_COLS + pxg * 8;
            const float* wrowc = g_wt + (size_t)(ch * CC + cl) * OC;
#pragma unroll
            for (int ky = 0; ky < 3; ky++) {
                float xv[10];
#pragma unroll
                for (int t = 0; t < 10; t++) xv[t] = srow[ky * IN_COLS + t];
#pragma unroll
                for (int kx = 0; kx < 3; kx++) {
                    const int tap = ky * 3 + kx;
                    const float* wp = wrowc + (size_t)tap * C_IN * OC + ocg * 2;
                    unsigned long long wv[4];
#pragma unroll
                    for (int i = 0; i < 4; i++)
                        wv[i] = *reinterpret_cast<const unsigned long long*>(wp + 128 * i);
#pragma unroll
                    for (int j = 0; j < 8; j++) {
                        unsigned long long xx = dup_f32(xv[j + kx]);
#pragma unroll
                        for (int i = 0; i < 4; i++) fma2(acc[i][j], wv[i], xx);
                    }
                }
            }
        }
    }

    // bias + ReLU, scatter feat tile to smem (px-major for float4 head reads)
#pragma unroll
    for (int i = 0; i < 4; i++) {
        const int o0 = ocg * 2 + 128 * i;
        const float bia0 = b1[o0];
        const float bia1 = b1[o0 + 1];
#pragma unroll
        for (int j = 0; j < 8; j++) {
            const int px = pxg * 8 + j;
            float lo = __uint_as_float((unsigned)(acc[i][j] & 0xffffffffull));
            float hi = __uint_as_float((unsigned)(acc[i][j] >> 32));
            feat[px * FEAT_STRIDE + o0]     = fmaxf(lo + bia0, 0.0f);
            feat[px * FEAT_STRIDE + o0 + 1] = fmaxf(hi + bia1, 0.0f);
        }
    }
    __syncthreads();

    // fused 1x1 heads: 54 outputs per pixel (18 cls + 36 box)
    const int px = tid % TILE_X;     // 0..55
    const int hb = tid / TILE_X;     // 0..7
    const int nho = (hb < 6) ? 7 : 6;  // ho = hb + 8k < 54

    const float* fp = feat + px * FEAT_STRIDE;
    float hacc[7];
    const float* wrow[7];
#pragma unroll
    for (int k = 0; k < 7; k++) {
        if (k < nho) {
            const int ho = hb + 8 * k;
            if (ho < CLS_CH) { wrow[k] = Wc + ho * OC;            hacc[k] = bc[ho]; }
            else             { wrow[k] = Wb + (ho - CLS_CH) * OC; hacc[k] = bb[ho - CLS_CH]; }
        } else { wrow[k] = Wc; hacc[k] = 0.0f; }
    }

    for (int o = 0; o < OC; o += 4) {
        const float4 f = *reinterpret_cast<const float4*>(fp + o);
#pragma unroll
        for (int k = 0; k < 7; k++) {
            if (k < nho) {
                const float4 w = *reinterpret_cast<const float4*>(wrow[k] + o);
                hacc[k] += f.x * w.x + f.y * w.y + f.z * w.z + f.w * w.w;
            }
        }
    }

    const size_t pix = ((size_t)(b * H_ + y)) * W_ + (x0 + px);
#pragma unroll
    for (int k = 0; k < 7; k++) {
        if (k < nho) {
            const int ho = hb + 8 * k;
            if (ho < CLS_CH) out[pix * CLS_CH + ho] = hacc[k];
            else             out[CLS_TOTAL + pix * 36 + (ho - CLS_CH)] = hacc[k];
        }
    }
}

extern "C" void kernel_launch(void* const* d_in, const int* in_sizes, int n_in,
                              void* d_out, int out_size) {
    const float* xf  = (const float*)d_in[0];
    const float* W1  = (const float*)d_in[1];
    const float* b1v = (const float*)d_in[2];
    const float* Wc  = (const float*)d_in[3];
    const float* bc  = (const float*)d_in[4];
    const float* Wb  = (const float*)d_in[5];
    const float* bb  = (const float*)d_in[6];
    float* out = (float*)d_out;

    (void)in_sizes; (void)n_in; (void)out_size;

    // transpose conv weights into [tap][c][o] (coalesced, pair-contiguous)
    const int wtotal = NTAP * C_IN * OC;
    prep_weights<<<(wtotal + 255) / 256, 256>>>(W1);

    // executes immediately (not a stream op) — legal during graph capture
    cudaFuncSetAttribute(rpn_fused,
                         cudaFuncAttributeMaxDynamicSharedMemorySize, SMEM_BYTES);

    dim3 grid(W_ / TILE_X, H_, B_);   // 6 x 200 x 4 = 4800 blocks
    rpn_fused<<<grid, NTHREADS, SMEM_BYTES>>>(xf, b1v, Wc, bc, Wb, bb, out);
}